// round 1
// baseline (speedup 1.0000x reference)
#include <cuda_runtime.h>

// Constants from the reference
#define EPS     1e-10f
#define B_CONST (1.0f + 0.1f + 0.05f)   // 1.15
#define BR      (1.0f + 0.1f - 0.05f)   // 1.05
#define HW      (512 * 512)

// Precomputed luminance table and its reciprocal (scratch: __device__ globals,
// allocation-free per the harness rules).
__device__ float g_v[HW];
__device__ float g_vinv[HW];

__global__ void build_v_kernel(const float* __restrict__ vin) {
    int i = blockIdx.x * blockDim.x + threadIdx.x;
    if (i < HW) {
        float v = (vin[i] + vin[i + HW] + vin[i + 2 * HW]) * (1.0f / 3.0f);
        v = (v * 255.0f + 1.0f) * (1.0f / 256.0f);
        g_v[i] = v;
        g_vinv[i] = __frcp_rn(v + EPS);
    }
}

__global__ void zero_out_kernel(float* out) {
    out[0] = 0.0f;
}

__global__ void __launch_bounds__(256) whdr_loss_kernel(
    const int4* __restrict__ coords,     // (N,4) int32 as int4: x1,y1,x2,y2
    const int*  __restrict__ darker,     // (N,)
    const float* __restrict__ weights,   // (N,)
    float* __restrict__ out,
    int n)
{
    const float inv_b = 1.0f / B_CONST;
    const float bl    = 1.0f / BR;
    const float inv_n = 1.0f / (float)n;

    float acc = 0.0f;

    int stride = gridDim.x * blockDim.x;
    #pragma unroll 4
    for (int i = blockIdx.x * blockDim.x + threadIdx.x; i < n; i += stride) {
        int4 c  = coords[i];
        int  d  = darker[i];
        float w = weights[i];

        int i1 = (c.y << 9) | c.x;   // y1*512 + x1
        int i2 = (c.w << 9) | c.z;   // y2*512 + x2

        float r1   = __ldg(&g_v[i1]);
        float r2   = __ldg(&g_v[i2]);
        float inv1 = __ldg(&g_vinv[i1]);
        float inv2 = __ldg(&g_vinv[i2]);

        float ratio     = r1 * inv2;   // r1 / (r2 + EPS)
        float ratio_inv = r2 * inv1;   // r2 / (r1 + EPS)

        float l1 = (ratio > inv_b) ? (ratio - inv_b + (B_CONST - ratio_inv)) : 0.0f;
        float l2 = (ratio < B_CONST) ? (B_CONST - ratio + (ratio_inv - inv_b)) : 0.0f;
        float l0 = (ratio > BR) ? (ratio - BR + (bl - ratio_inv))
                 : ((ratio < bl) ? (bl - ratio + (ratio_inv - BR)) : 0.0f);

        float per = (d == 1) ? l1 : ((d == 2) ? l2 : l0);
        acc += w * per;
    }

    // Warp reduction
    #pragma unroll
    for (int off = 16; off > 0; off >>= 1)
        acc += __shfl_xor_sync(0xffffffffu, acc, off);

    // Block reduction
    __shared__ float warp_sums[8];
    int lane = threadIdx.x & 31;
    int wid  = threadIdx.x >> 5;
    if (lane == 0) warp_sums[wid] = acc;
    __syncthreads();
    if (wid == 0) {
        float s = (lane < (blockDim.x >> 5)) ? warp_sums[lane] : 0.0f;
        #pragma unroll
        for (int off = 4; off > 0; off >>= 1)
            s += __shfl_xor_sync(0xffffffffu, s, off);
        if (lane == 0)
            atomicAdd(out, s * inv_n);
    }
}

extern "C" void kernel_launch(void* const* d_in, const int* in_sizes, int n_in,
                              void* d_out, int out_size)
{
    const float* vin     = (const float*)d_in[0];
    const int4*  coords  = (const int4*)d_in[1];
    const int*   darker  = (const int*)d_in[2];
    const float* weights = (const float*)d_in[3];
    float*       out     = (float*)d_out;

    int n = in_sizes[2];  // darker element count == N

    build_v_kernel<<<(HW + 255) / 256, 256>>>(vin);
    zero_out_kernel<<<1, 1>>>(out);

    int threads = 256;
    int blocks  = 2048;   // grid-stride; ~16 elements/thread
    whdr_loss_kernel<<<blocks, threads>>>(coords, darker, weights, out, n);
}

// round 2
// speedup vs baseline: 1.7793x; 1.7793x over previous
#include <cuda_runtime.h>

// Constants from the reference
#define EPS     1e-10f
#define B_CONST (1.0f + 0.1f + 0.05f)   // 1.15
#define BR      (1.0f + 0.1f - 0.05f)   // 1.05
#define HW      (512 * 512)

// Packed table: .x = v, .y = 1/(v+EPS). One 8B gather returns both values,
// halving L2 sector traffic vs two separate 4B tables.
__device__ float2 g_vv[HW];

__global__ void build_v_kernel(const float* __restrict__ vin, float* __restrict__ out) {
    int i = blockIdx.x * blockDim.x + threadIdx.x;
    if (i < HW) {
        float v = (vin[i] + vin[i + HW] + vin[i + 2 * HW]) * (1.0f / 3.0f);
        v = (v * 255.0f + 1.0f) * (1.0f / 256.0f);
        g_vv[i] = make_float2(v, __frcp_rn(v + EPS));
    }
    if (i == 0) out[0] = 0.0f;   // fold output zeroing into this kernel
}

__global__ void __launch_bounds__(256) whdr_loss_kernel(
    const int4*  __restrict__ coords,    // (N,4) int32 as int4: x1,y1,x2,y2
    const int*   __restrict__ darker,    // (N,)
    const float* __restrict__ weights,   // (N,)
    float* __restrict__ out,
    int n)
{
    const float inv_b = 1.0f / B_CONST;
    const float bl    = 1.0f / BR;
    const float inv_n = 1.0f / (float)n;

    float acc = 0.0f;

    int stride = gridDim.x * blockDim.x;
    #pragma unroll 4
    for (int i = blockIdx.x * blockDim.x + threadIdx.x; i < n; i += stride) {
        int4 c  = coords[i];
        int  d  = darker[i];
        float w = weights[i];

        int i1 = (c.y << 9) | c.x;   // y1*512 + x1
        int i2 = (c.w << 9) | c.z;   // y2*512 + x2

        float2 p1 = __ldg(&g_vv[i1]);   // (r1, 1/(r1+eps))
        float2 p2 = __ldg(&g_vv[i2]);   // (r2, 1/(r2+eps))

        float ratio     = p1.x * p2.y;  // r1 / (r2 + EPS)
        float ratio_inv = p2.x * p1.y;  // r2 / (r1 + EPS)

        float l1 = (ratio > inv_b)   ? (ratio - inv_b + (B_CONST - ratio_inv)) : 0.0f;
        float l2 = (ratio < B_CONST) ? (B_CONST - ratio + (ratio_inv - inv_b)) : 0.0f;
        float l0 = (ratio > BR) ? (ratio - BR + (bl - ratio_inv))
                 : ((ratio < bl) ? (bl - ratio + (ratio_inv - BR)) : 0.0f);

        float per = (d == 1) ? l1 : ((d == 2) ? l2 : l0);
        acc += w * per;
    }

    // Warp reduction
    #pragma unroll
    for (int off = 16; off > 0; off >>= 1)
        acc += __shfl_xor_sync(0xffffffffu, acc, off);

    // Block reduction (small smem so L1D carveout stays large for the table)
    __shared__ float warp_sums[8];
    int lane = threadIdx.x & 31;
    int wid  = threadIdx.x >> 5;
    if (lane == 0) warp_sums[wid] = acc;
    __syncthreads();
    if (wid == 0) {
        float s = (lane < (blockDim.x >> 5)) ? warp_sums[lane] : 0.0f;
        #pragma unroll
        for (int off = 4; off > 0; off >>= 1)
            s += __shfl_xor_sync(0xffffffffu, s, off);
        if (lane == 0)
            atomicAdd(out, s * inv_n);
    }
}

extern "C" void kernel_launch(void* const* d_in, const int* in_sizes, int n_in,
                              void* d_out, int out_size)
{
    const float* vin     = (const float*)d_in[0];
    const int4*  coords  = (const int4*)d_in[1];
    const int*   darker  = (const int*)d_in[2];
    const float* weights = (const float*)d_in[3];
    float*       out     = (float*)d_out;

    int n = in_sizes[2];  // darker element count == N

    build_v_kernel<<<(HW + 255) / 256, 256>>>(vin, out);

    int threads = 256;
    int blocks  = 2048;   // grid-stride; ~16 elements/thread
    whdr_loss_kernel<<<blocks, threads>>>(coords, darker, weights, out, n);
}